// round 16
// baseline (speedup 1.0000x reference)
#include <cuda_runtime.h>
#include <math.h>

#define MAXN 10000
#define MAXE 320000

// Scratch (__device__ globals per allocation-free rule)
__device__ float4 g_y4[MAXN * 64];    // [node][u] = (y0, y1x, y1y, y1z), scale 1/8 folded
__device__ float  g_agg[MAXN * 512];  // reference concat layout, LIN2S (1/64) folded
__device__ float4 g_erec[MAXE * 4];   // packed CSR edge record: [sh | h0..3 | h4..7 | src,pad]
__device__ int    g_deg[MAXN];        // zero-invariant between calls (scan re-zeroes)
__device__ int    g_row[MAXN + 1];
__device__ int    g_cursor[MAXN];

#define INV_SQRT8 0.35355339059327373f
#define INV_SQRT3 0.5773502691896258f
#define LOG2F_C   0.6931471805599453f
#define LIN2S     0.015625f   // 1/(sqrt(32)*sqrt(128))
#define SCN       0.0625f     // 1/sqrt(64*4)

// ---------------------------------------------------------------------------
// Fused launch 0: blocks [0, cb) = degree count; blocks [cb, ...) = node-pre GEMMs.
__global__ void fused_count_pre_kernel(const int* __restrict__ eidx,
                                       const float* __restrict__ nf,
                                       const float* __restrict__ Wl10,
                                       const float* __restrict__ Wl11,
                                       int E, int n, int cb, int nb0) {
    __shared__ __align__(16) float sIn[32 * 64];
    __shared__ __align__(16) float sW[64 * 64];
    int tid = threadIdx.x;

    if (blockIdx.x < cb) {
        int e = blockIdx.x * 256 + tid;
        if (e < E) atomicAdd(&g_deg[eidx[e]], 1);
        return;
    }

    int bx = blockIdx.x - cb;
    int v = tid & 63, rgrp = tid >> 6;
    int mode = (bx >= nb0) ? 1 : 0;
    int blk = mode ? (bx - nb0) : bx;
    int rows = mode ? 3 * n : n;
    int rbase = blk * 32;
    const float* W = mode ? Wl11 : Wl10;

    for (int i = tid; i < 4096; i += 256) sW[i] = W[i];
    for (int i = tid; i < 2048; i += 256) {
        int row = i >> 6, k = i & 63;
        int rg = rbase + row;
        float val = 0.f;
        if (rg < rows) {
            if (mode == 0) val = nf[(size_t)rg * 256 + k];
            else {
                int node = rg / 3, m = rg % 3;
                val = nf[(size_t)node * 256 + 64 + k * 3 + m];
            }
        }
        sIn[i] = val;
    }
    __syncthreads();

    float acc[8] = {0.f, 0.f, 0.f, 0.f, 0.f, 0.f, 0.f, 0.f};
    for (int kk = 0; kk < 64; kk += 4) {
        float w0 = sW[(kk + 0) * 64 + v];
        float w1 = sW[(kk + 1) * 64 + v];
        float w2 = sW[(kk + 2) * 64 + v];
        float w3 = sW[(kk + 3) * 64 + v];
        #pragma unroll
        for (int r = 0; r < 8; ++r) {
            const float4 in4 = *(const float4*)(sIn + (rgrp * 8 + r) * 64 + kk);
            acc[r] = fmaf(in4.x, w0, fmaf(in4.y, w1, fmaf(in4.z, w2, fmaf(in4.w, w3, acc[r]))));
        }
    }
    float* gy = (float*)g_y4;
    #pragma unroll
    for (int r = 0; r < 8; ++r) {
        int rg = rbase + rgrp * 8 + r;
        if (rg >= rows) continue;
        float val = acc[r] * 0.125f;
        if (mode == 0) gy[((size_t)rg * 64 + v) * 4 + 0] = val;
        else {
            int node = rg / 3, m = rg % 3;
            gy[((size_t)node * 64 + v) * 4 + 1 + m] = val;
        }
    }
}

// Single-block scan g_deg -> g_row, g_cursor; re-zeroes g_deg for the next call.
__global__ void scan_kernel(int n) {
    __shared__ int part[1024];
    int tid = threadIdx.x;
    int IT = (n + 1023) >> 10;
    int base = tid * IT;
    int degs[16];
    int s = 0;
    for (int i = 0; i < IT; ++i) {
        int idx = base + i;
        degs[i] = (idx < n) ? g_deg[idx] : 0;
        s += degs[i];
    }
    part[tid] = s;
    __syncthreads();
    for (int off = 1; off < 1024; off <<= 1) {
        int v = (tid >= off) ? part[tid - off] : 0;
        __syncthreads();
        part[tid] += v;
        __syncthreads();
    }
    int run = part[tid] - s;
    for (int i = 0; i < IT; ++i) {
        int idx = base + i;
        if (idx < n) {
            g_row[idx] = run;
            g_cursor[idx] = run;
            run += degs[i];
            g_deg[idx] = 0;             // restore zero-invariant
        }
    }
    if (tid == 1023) g_row[n] = part[1023];
}

// Fused: per-edge MLP hidden layer h + CSR scatter of the PACKED 64B record.
__global__ void scatter_h_kernel(const int* __restrict__ eidx,
                                 const float* __restrict__ eemb,
                                 const float* __restrict__ eattr,
                                 const float* __restrict__ Wfc1,
                                 int E) {
    __shared__ float sW1[64];
    int tid = threadIdx.x;
    if (tid < 64) sW1[tid] = Wfc1[tid];
    __syncthreads();
    int e = blockIdx.x * blockDim.x + tid;
    if (e >= E) return;

    int dst = __ldg(eidx + e);
    int src = __ldg(eidx + E + e);
    int pos = atomicAdd(&g_cursor[dst], 1);

    float4 sh = __ldg((const float4*)(eattr + (size_t)e * 4));
    float4 e0 = *(const float4*)(eemb + (size_t)e * 8);
    float4 e1 = *(const float4*)(eemb + (size_t)e * 8 + 4);
    float emb[8] = {e0.x, e0.y, e0.z, e0.w, e1.x, e1.y, e1.z, e1.w};
    float h[8];
    #pragma unroll
    for (int j = 0; j < 8; ++j) {
        float z = 0.f;
        #pragma unroll
        for (int k = 0; k < 8; ++k) z = fmaf(emb[k], sW1[k * 8 + j], z);
        z *= INV_SQRT8;
        float sp = (z > 20.f) ? z : log1pf(__expf(z));
        h[j] = (sp - LOG2F_C) * INV_SQRT8;
    }

    float4* rp = g_erec + (size_t)pos * 4;
    rp[0] = sh;
    rp[1] = make_float4(h[0], h[1], h[2], h[3]);
    rp[2] = make_float4(h[4], h[5], h[6], h[7]);
    rp[3] = make_float4(__int_as_float(src), 0.f, 0.f, 0.f);
}

// ---------------------------------------------------------------------------
// Aggregation v5: 128-thread block per node, split weights across halves.
//   half 0 (t<64): owns w1,w2 -> a0 (mid_s0) and a2..a4 (mid_v0)
//   half 1 (t>=64): owns w3,w4 -> a1 (mid_s1, 1/sqrt3 folded) and a5..a7 (mid_v1)
// ~44 regs/thread -> ~11 blocks/SM (68% occ ceiling). No smem, no barriers.
__global__ void __launch_bounds__(128) agg_kernel(const float* __restrict__ Wfc2, int n) {
    int t = threadIdx.x;
    int u = t & 63;
    int half = t >> 6;       // warps 0,1 = half 0; warps 2,3 = half 1 (no divergence)
    int node = blockIdx.x;

    // 16 weight regs per thread: wX = w1|w3 column, wY = w2|w4 column (w4 *1/sqrt3)
    float wX[8], wY[8];
    float fold = half ? INV_SQRT3 : 1.0f;
    #pragma unroll
    for (int j = 0; j < 8; ++j) {
        const float* r = Wfc2 + j * 256 + half * 128;
        wX[j] = __ldg(r + u);
        wY[j] = __ldg(r + 64 + u) * fold;
    }

    int rs = g_row[node], re = g_row[node + 1];

    float a0 = 0.f, aP = 0.f, aQ = 0.f, aR = 0.f;

    for (int i = rs; i < re; ++i) {
        const float4* rp = g_erec + (size_t)i * 4;   // sequential per node, uniform per block
        float4 sh = __ldg(rp);
        float4 h0 = __ldg(rp + 1);
        float4 h1 = __ldg(rp + 2);
        int src = __float_as_int(__ldg((const float*)(rp + 3)));
        float4 y4 = __ldg(g_y4 + (size_t)src * 64 + u); // dup across halves -> L1 hit

        float p = fmaf(h0.x, wX[0], fmaf(h0.y, wX[1], fmaf(h0.z, wX[2], fmaf(h0.w, wX[3],
                  fmaf(h1.x, wX[4], fmaf(h1.y, wX[5], fmaf(h1.z, wX[6], h1.w * wX[7])))))));
        float q = fmaf(h0.x, wY[0], fmaf(h0.y, wY[1], fmaf(h0.z, wY[2], fmaf(h0.w, wY[3],
                  fmaf(h1.x, wY[4], fmaf(h1.y, wY[5], fmaf(h1.z, wY[6], h1.w * wY[7])))))));

        if (half == 0) {
            // p = w1, q = w2
            float a2c = q * y4.x;                 // w2 * xs0
            a0 = fmaf(p * y4.x, sh.x, a0);        // w1 * xs0 * sh0
            aP = fmaf(a2c, sh.y, aP);
            aQ = fmaf(a2c, sh.z, aQ);
            aR = fmaf(a2c, sh.w, aR);
        } else {
            // p = w3, q = w4 * 1/sqrt3
            float dotv = fmaf(y4.y, sh.y, fmaf(y4.z, sh.z, y4.w * sh.w));
            float a3c = p * sh.x;                 // w3 * sh0
            a0 = fmaf(q, dotv, a0);               // w4' * dotv
            aP = fmaf(a3c, y4.y, aP);
            aQ = fmaf(a3c, y4.z, aQ);
            aR = fmaf(a3c, y4.w, aR);
        }
    }

    float* arow = g_agg + (size_t)node * 512;
    if (half == 0) {
        arow[u]               = a0 * LIN2S;
        arow[128 + 3 * u + 0] = aP * LIN2S;
        arow[128 + 3 * u + 1] = aQ * LIN2S;
        arow[128 + 3 * u + 2] = aR * LIN2S;
    } else {
        arow[64 + u]          = a0 * LIN2S;
        arow[320 + 3 * u + 0] = aP * LIN2S;
        arow[320 + 3 * u + 1] = aQ * LIN2S;
        arow[320 + 3 * u + 2] = aR * LIN2S;
    }
}

// ---------------------------------------------------------------------------
// Node post GEMM, K=384 (3 chunks of 128): [agg_part | attrs (x) x] @ [W_lin2 ; W_sc].
__global__ void post_gemm_kernel(const float* __restrict__ nf,
                                 const float* __restrict__ attrs,
                                 const float* __restrict__ Wl20,
                                 const float* __restrict__ Wl21,
                                 const float* __restrict__ Wsc0,
                                 const float* __restrict__ Wsc1,
                                 float* __restrict__ out,
                                 int n, int nb0) {
    __shared__ __align__(16) float sIn[32 * 128];   // 16 KB
    __shared__ __align__(16) float sW[128 * 64];    // 32 KB
    int tid = threadIdx.x;
    int v = tid & 63, rgrp = tid >> 6;
    int mode = (blockIdx.x >= nb0) ? 1 : 0;
    int blk = mode ? (blockIdx.x - nb0) : blockIdx.x;
    int rows = mode ? 3 * n : n;
    int rbase = blk * 32;
    const float* Wlin = mode ? Wl21 : Wl20;
    const float* Wsc  = mode ? Wsc1 : Wsc0;

    float acc[8] = {0.f, 0.f, 0.f, 0.f, 0.f, 0.f, 0.f, 0.f};

    for (int c = 0; c < 3; ++c) {
        for (int i = tid; i < 8192; i += 256) {
            int kk = i >> 6, vv = i & 63;
            int k = c * 128 + kk;
            float w;
            if (k < 128) w = Wlin[k * 64 + vv];
            else {
                int t2 = k - 128, a = t2 >> 6, uu = t2 & 63;
                w = Wsc[uu * 256 + a * 64 + vv];
            }
            sW[i] = w;
        }
        for (int i = tid; i < 4096; i += 256) {
            int row = i >> 7, kk = i & 127;
            int rg = rbase + row;
            int k = c * 128 + kk;
            float val = 0.f;
            if (rg < rows) {
                if (mode == 0) {
                    if (k < 128) val = g_agg[(size_t)rg * 512 + k];
                    else {
                        int t2 = k - 128, a = t2 >> 6, uu = t2 & 63;
                        val = attrs[(size_t)rg * 4 + a] * nf[(size_t)rg * 256 + uu] * SCN;
                    }
                } else {
                    int node = rg / 3, m = rg % 3;
                    if (k < 128) val = g_agg[(size_t)node * 512 + 128 + k * 3 + m];
                    else {
                        int t2 = k - 128, a = t2 >> 6, uu = t2 & 63;
                        val = attrs[(size_t)node * 4 + a] * nf[(size_t)node * 256 + 64 + uu * 3 + m] * SCN;
                    }
                }
            }
            sIn[i] = val;
        }
        __syncthreads();

        for (int kk = 0; kk < 128; kk += 4) {
            float w0 = sW[(kk + 0) * 64 + v];
            float w1 = sW[(kk + 1) * 64 + v];
            float w2 = sW[(kk + 2) * 64 + v];
            float w3 = sW[(kk + 3) * 64 + v];
            #pragma unroll
            for (int r = 0; r < 8; ++r) {
                const float4 in4 = *(const float4*)(sIn + (rgrp * 8 + r) * 128 + kk);
                acc[r] = fmaf(in4.x, w0, fmaf(in4.y, w1, fmaf(in4.z, w2, fmaf(in4.w, w3, acc[r]))));
            }
        }
        __syncthreads();
    }

    #pragma unroll
    for (int r = 0; r < 8; ++r) {
        int rg = rbase + rgrp * 8 + r;
        if (rg >= rows) continue;
        if (mode == 0) out[(size_t)rg * 256 + v] = acc[r];
        else {
            int node = rg / 3, m = rg % 3;
            out[(size_t)node * 256 + 64 + v * 3 + m] = acc[r];
        }
    }
}

// ---------------------------------------------------------------------------
extern "C" void kernel_launch(void* const* d_in, const int* in_sizes, int n_in,
                              void* d_out, int out_size) {
    const float* nf    = (const float*)d_in[0];
    const float* attrs = (const float*)d_in[1];
    const float* ea    = (const float*)d_in[2];
    const float* ee    = (const float*)d_in[3];
    const int*   ei    = (const int*)d_in[4];
    const float* Wl10  = (const float*)d_in[5];
    const float* Wl11  = (const float*)d_in[6];
    const float* Wfc1  = (const float*)d_in[7];
    const float* Wfc2  = (const float*)d_in[8];
    const float* Wl20  = (const float*)d_in[9];
    const float* Wl21  = (const float*)d_in[10];
    const float* Wsc0  = (const float*)d_in[11];
    const float* Wsc1  = (const float*)d_in[12];
    float* out = (float*)d_out;

    int n = in_sizes[0] / 256;
    int E = in_sizes[2] / 4;

    // launch 0: fused degree count + node-pre GEMMs (independent)
    int cb = (E + 255) / 256;
    int pre_nb0 = (n + 31) / 32, pre_nb1 = (3 * n + 31) / 32;
    fused_count_pre_kernel<<<cb + pre_nb0 + pre_nb1, 256>>>(
        ei, nf, Wl10, Wl11, E, n, cb, pre_nb0);
    // launch 1: scan -> row/cursor, re-zero g_deg
    scan_kernel<<<1, 1024>>>(n);
    // launch 2: edge MLP + packed-record scatter
    scatter_h_kernel<<<(E + 255) / 256, 256>>>(ei, ee, ea, Wfc1, E);
    // launch 3: aggregation (split-weight, 128 threads/node) — profiled slot
    agg_kernel<<<n, 128>>>(Wfc2, n);
    // launch 4: node post
    int post_nb0 = (n + 31) / 32, post_nb1 = (3 * n + 31) / 32;
    post_gemm_kernel<<<post_nb0 + post_nb1, 256>>>(nf, attrs, Wl20, Wl21, Wsc0, Wsc1, out, n, post_nb0);
}

// round 17
// speedup vs baseline: 1.1495x; 1.1495x over previous
#include <cuda_runtime.h>
#include <math.h>

#define MAXN 10000
#define MAXE 320000

// Scratch (__device__ globals per allocation-free rule)
__device__ float4 g_y4[MAXN * 64];    // [node][u] = (y0, y1x, y1y, y1z), scale 1/8 folded
__device__ float  g_agg[MAXN * 512];  // reference concat layout, LIN2S (1/64) folded
__device__ float4 g_erec[MAXE * 4];   // packed CSR edge record: [sh | h0..3 | h4..7 | src,pad]
__device__ int    g_deg[MAXN];        // zero-invariant between calls (scan re-zeroes)
__device__ int    g_row[MAXN + 1];
__device__ int    g_cursor[MAXN];

#define INV_SQRT8 0.35355339059327373f
#define INV_SQRT3 0.5773502691896258f
#define LOG2F_C   0.6931471805599453f
#define LIN2S     0.015625f   // 1/(sqrt(32)*sqrt(128))
#define SCN       0.0625f     // 1/sqrt(64*4)

// ---------------------------------------------------------------------------
// Fused launch 0: blocks [0, cb) = degree count; blocks [cb, ...) = node-pre GEMMs.
__global__ void fused_count_pre_kernel(const int* __restrict__ eidx,
                                       const float* __restrict__ nf,
                                       const float* __restrict__ Wl10,
                                       const float* __restrict__ Wl11,
                                       int E, int n, int cb, int nb0) {
    __shared__ __align__(16) float sIn[32 * 64];
    __shared__ __align__(16) float sW[64 * 64];
    int tid = threadIdx.x;

    if (blockIdx.x < cb) {
        int e = blockIdx.x * 256 + tid;
        if (e < E) atomicAdd(&g_deg[eidx[e]], 1);
        return;
    }

    int bx = blockIdx.x - cb;
    int v = tid & 63, rgrp = tid >> 6;
    int mode = (bx >= nb0) ? 1 : 0;
    int blk = mode ? (bx - nb0) : bx;
    int rows = mode ? 3 * n : n;
    int rbase = blk * 32;
    const float* W = mode ? Wl11 : Wl10;

    for (int i = tid; i < 4096; i += 256) sW[i] = W[i];
    for (int i = tid; i < 2048; i += 256) {
        int row = i >> 6, k = i & 63;
        int rg = rbase + row;
        float val = 0.f;
        if (rg < rows) {
            if (mode == 0) val = nf[(size_t)rg * 256 + k];
            else {
                int node = rg / 3, m = rg % 3;
                val = nf[(size_t)node * 256 + 64 + k * 3 + m];
            }
        }
        sIn[i] = val;
    }
    __syncthreads();

    float acc[8] = {0.f, 0.f, 0.f, 0.f, 0.f, 0.f, 0.f, 0.f};
    for (int kk = 0; kk < 64; kk += 4) {
        float w0 = sW[(kk + 0) * 64 + v];
        float w1 = sW[(kk + 1) * 64 + v];
        float w2 = sW[(kk + 2) * 64 + v];
        float w3 = sW[(kk + 3) * 64 + v];
        #pragma unroll
        for (int r = 0; r < 8; ++r) {
            const float4 in4 = *(const float4*)(sIn + (rgrp * 8 + r) * 64 + kk);
            acc[r] = fmaf(in4.x, w0, fmaf(in4.y, w1, fmaf(in4.z, w2, fmaf(in4.w, w3, acc[r]))));
        }
    }
    float* gy = (float*)g_y4;
    #pragma unroll
    for (int r = 0; r < 8; ++r) {
        int rg = rbase + rgrp * 8 + r;
        if (rg >= rows) continue;
        float val = acc[r] * 0.125f;
        if (mode == 0) gy[((size_t)rg * 64 + v) * 4 + 0] = val;
        else {
            int node = rg / 3, m = rg % 3;
            gy[((size_t)node * 64 + v) * 4 + 1 + m] = val;
        }
    }
}

// Single-block scan g_deg -> g_row, g_cursor; re-zeroes g_deg for the next call.
__global__ void scan_kernel(int n) {
    __shared__ int part[1024];
    int tid = threadIdx.x;
    int IT = (n + 1023) >> 10;
    int base = tid * IT;
    int degs[16];
    int s = 0;
    for (int i = 0; i < IT; ++i) {
        int idx = base + i;
        degs[i] = (idx < n) ? g_deg[idx] : 0;
        s += degs[i];
    }
    part[tid] = s;
    __syncthreads();
    for (int off = 1; off < 1024; off <<= 1) {
        int v = (tid >= off) ? part[tid - off] : 0;
        __syncthreads();
        part[tid] += v;
        __syncthreads();
    }
    int run = part[tid] - s;
    for (int i = 0; i < IT; ++i) {
        int idx = base + i;
        if (idx < n) {
            g_row[idx] = run;
            g_cursor[idx] = run;
            run += degs[i];
            g_deg[idx] = 0;             // restore zero-invariant
        }
    }
    if (tid == 1023) g_row[n] = part[1023];
}

// Fused: per-edge MLP hidden layer h + CSR scatter of the PACKED 64B record.
__global__ void scatter_h_kernel(const int* __restrict__ eidx,
                                 const float* __restrict__ eemb,
                                 const float* __restrict__ eattr,
                                 const float* __restrict__ Wfc1,
                                 int E) {
    __shared__ float sW1[64];
    int tid = threadIdx.x;
    if (tid < 64) sW1[tid] = Wfc1[tid];
    __syncthreads();
    int e = blockIdx.x * blockDim.x + tid;
    if (e >= E) return;

    int dst = __ldg(eidx + e);
    int src = __ldg(eidx + E + e);
    int pos = atomicAdd(&g_cursor[dst], 1);

    float4 sh = __ldg((const float4*)(eattr + (size_t)e * 4));
    float4 e0 = *(const float4*)(eemb + (size_t)e * 8);
    float4 e1 = *(const float4*)(eemb + (size_t)e * 8 + 4);
    float emb[8] = {e0.x, e0.y, e0.z, e0.w, e1.x, e1.y, e1.z, e1.w};
    float h[8];
    #pragma unroll
    for (int j = 0; j < 8; ++j) {
        float z = 0.f;
        #pragma unroll
        for (int k = 0; k < 8; ++k) z = fmaf(emb[k], sW1[k * 8 + j], z);
        z *= INV_SQRT8;
        float sp = (z > 20.f) ? z : log1pf(__expf(z));
        h[j] = (sp - LOG2F_C) * INV_SQRT8;
    }

    float4* rp = g_erec + (size_t)pos * 4;
    rp[0] = sh;
    rp[1] = make_float4(h[0], h[1], h[2], h[3]);
    rp[2] = make_float4(h[4], h[5], h[6], h[7]);
    rp[3] = make_float4(__int_as_float(src), 0.f, 0.f, 0.f);
}

// ---------------------------------------------------------------------------
// Aggregation v6: 64-thread block per node (R14 base), SOFTWARE-PIPELINED loop.
// Stage A: math operands (arrived >=1 iter ago). Stage B: record in flight + its
// y4 issued this iter. Stage C: record issued this iter. Exposed latency ~0.
__global__ void __launch_bounds__(64) agg_kernel(const float* __restrict__ Wfc2, int n) {
    int u = threadIdx.x;
    int node = blockIdx.x;

    // Per-thread weight columns (coalesced, once). 1/sqrt3 folded into wD.
    float wA[8], wB[8], wC[8], wD[8];
    #pragma unroll
    for (int j = 0; j < 8; ++j) {
        const float* r = Wfc2 + j * 256;
        wA[j] = __ldg(r + u);
        wB[j] = __ldg(r + 64 + u);
        wC[j] = __ldg(r + 128 + u);
        wD[j] = __ldg(r + 192 + u) * INV_SQRT3;
    }

    int rs = g_row[node], re = g_row[node + 1];

    float a0 = 0.f, a1 = 0.f, a2 = 0.f, a3 = 0.f, a4 = 0.f, a5 = 0.f, a6 = 0.f, a7 = 0.f;

    if (rs < re) {
        // Prologue: edge rs fully loaded; edge rs+1 record in flight.
        const float4* rp = g_erec + (size_t)rs * 4;
        float4 shA = __ldg(rp);
        float4 h0A = __ldg(rp + 1);
        float4 h1A = __ldg(rp + 2);
        int srcA = __float_as_int(__ldg((const float*)(rp + 3)));
        float4 yA = __ldg(g_y4 + (size_t)srcA * 64 + u);

        int j1 = (rs + 1 < re) ? rs + 1 : rs;
        const float4* rq = g_erec + (size_t)j1 * 4;
        float4 shB = __ldg(rq);
        float4 h0B = __ldg(rq + 1);
        float4 h1B = __ldg(rq + 2);
        int srcB = __float_as_int(__ldg((const float*)(rq + 3)));

        #pragma unroll 2
        for (int i = rs; i < re; ++i) {
            // Issue next y (src arrived last iteration) and record i+2.
            float4 yB = __ldg(g_y4 + (size_t)srcB * 64 + u);
            int j2 = (i + 2 < re) ? i + 2 : rs;
            const float4* rc = g_erec + (size_t)j2 * 4;
            float4 shC = __ldg(rc);
            float4 h0C = __ldg(rc + 1);
            float4 h1C = __ldg(rc + 2);
            int srcC = __float_as_int(__ldg((const float*)(rc + 3)));

            // Math on edge i (operands arrived >=1 iteration ago).
            float w1 = fmaf(h0A.x, wA[0], fmaf(h0A.y, wA[1], fmaf(h0A.z, wA[2], fmaf(h0A.w, wA[3],
                       fmaf(h1A.x, wA[4], fmaf(h1A.y, wA[5], fmaf(h1A.z, wA[6], h1A.w * wA[7])))))));
            float w2 = fmaf(h0A.x, wB[0], fmaf(h0A.y, wB[1], fmaf(h0A.z, wB[2], fmaf(h0A.w, wB[3],
                       fmaf(h1A.x, wB[4], fmaf(h1A.y, wB[5], fmaf(h1A.z, wB[6], h1A.w * wB[7])))))));
            float w3 = fmaf(h0A.x, wC[0], fmaf(h0A.y, wC[1], fmaf(h0A.z, wC[2], fmaf(h0A.w, wC[3],
                       fmaf(h1A.x, wC[4], fmaf(h1A.y, wC[5], fmaf(h1A.z, wC[6], h1A.w * wC[7])))))));
            float w4 = fmaf(h0A.x, wD[0], fmaf(h0A.y, wD[1], fmaf(h0A.z, wD[2], fmaf(h0A.w, wD[3],
                       fmaf(h1A.x, wD[4], fmaf(h1A.y, wD[5], fmaf(h1A.z, wD[6], h1A.w * wD[7])))))));

            float xs0 = yA.x, x1x = yA.y, x1y = yA.z, x1z = yA.w;
            float dotv = fmaf(x1x, shA.y, fmaf(x1y, shA.z, x1z * shA.w));
            float a2c = w2 * xs0;
            float a3c = w3 * shA.x;
            a0 = fmaf(w1 * xs0, shA.x, a0);
            a1 = fmaf(w4, dotv, a1);
            a2 = fmaf(a2c, shA.y, a2);
            a3 = fmaf(a2c, shA.z, a3);
            a4 = fmaf(a2c, shA.w, a4);
            a5 = fmaf(a3c, x1x, a5);
            a6 = fmaf(a3c, x1y, a6);
            a7 = fmaf(a3c, x1z, a7);

            // Rotate pipeline registers.
            shA = shB; h0A = h0B; h1A = h1B; yA = yB;
            shB = shC; h0B = h0C; h1B = h1C; srcB = srcC;
        }
    }

    float* arow = g_agg + (size_t)node * 512;
    arow[u]               = a0 * LIN2S;
    arow[64 + u]          = a1 * LIN2S;
    arow[128 + 3 * u + 0] = a2 * LIN2S;
    arow[128 + 3 * u + 1] = a3 * LIN2S;
    arow[128 + 3 * u + 2] = a4 * LIN2S;
    arow[320 + 3 * u + 0] = a5 * LIN2S;
    arow[320 + 3 * u + 1] = a6 * LIN2S;
    arow[320 + 3 * u + 2] = a7 * LIN2S;
}

// ---------------------------------------------------------------------------
// Node post GEMM, K=384 (3 chunks of 128): [agg_part | attrs (x) x] @ [W_lin2 ; W_sc].
__global__ void post_gemm_kernel(const float* __restrict__ nf,
                                 const float* __restrict__ attrs,
                                 const float* __restrict__ Wl20,
                                 const float* __restrict__ Wl21,
                                 const float* __restrict__ Wsc0,
                                 const float* __restrict__ Wsc1,
                                 float* __restrict__ out,
                                 int n, int nb0) {
    __shared__ __align__(16) float sIn[32 * 128];   // 16 KB
    __shared__ __align__(16) float sW[128 * 64];    // 32 KB
    int tid = threadIdx.x;
    int v = tid & 63, rgrp = tid >> 6;
    int mode = (blockIdx.x >= nb0) ? 1 : 0;
    int blk = mode ? (blockIdx.x - nb0) : blockIdx.x;
    int rows = mode ? 3 * n : n;
    int rbase = blk * 32;
    const float* Wlin = mode ? Wl21 : Wl20;
    const float* Wsc  = mode ? Wsc1 : Wsc0;

    float acc[8] = {0.f, 0.f, 0.f, 0.f, 0.f, 0.f, 0.f, 0.f};

    for (int c = 0; c < 3; ++c) {
        for (int i = tid; i < 8192; i += 256) {
            int kk = i >> 6, vv = i & 63;
            int k = c * 128 + kk;
            float w;
            if (k < 128) w = Wlin[k * 64 + vv];
            else {
                int t2 = k - 128, a = t2 >> 6, uu = t2 & 63;
                w = Wsc[uu * 256 + a * 64 + vv];
            }
            sW[i] = w;
        }
        for (int i = tid; i < 4096; i += 256) {
            int row = i >> 7, kk = i & 127;
            int rg = rbase + row;
            int k = c * 128 + kk;
            float val = 0.f;
            if (rg < rows) {
                if (mode == 0) {
                    if (k < 128) val = g_agg[(size_t)rg * 512 + k];
                    else {
                        int t2 = k - 128, a = t2 >> 6, uu = t2 & 63;
                        val = attrs[(size_t)rg * 4 + a] * nf[(size_t)rg * 256 + uu] * SCN;
                    }
                } else {
                    int node = rg / 3, m = rg % 3;
                    if (k < 128) val = g_agg[(size_t)node * 512 + 128 + k * 3 + m];
                    else {
                        int t2 = k - 128, a = t2 >> 6, uu = t2 & 63;
                        val = attrs[(size_t)node * 4 + a] * nf[(size_t)node * 256 + 64 + uu * 3 + m] * SCN;
                    }
                }
            }
            sIn[i] = val;
        }
        __syncthreads();

        for (int kk = 0; kk < 128; kk += 4) {
            float w0 = sW[(kk + 0) * 64 + v];
            float w1 = sW[(kk + 1) * 64 + v];
            float w2 = sW[(kk + 2) * 64 + v];
            float w3 = sW[(kk + 3) * 64 + v];
            #pragma unroll
            for (int r = 0; r < 8; ++r) {
                const float4 in4 = *(const float4*)(sIn + (rgrp * 8 + r) * 128 + kk);
                acc[r] = fmaf(in4.x, w0, fmaf(in4.y, w1, fmaf(in4.z, w2, fmaf(in4.w, w3, acc[r]))));
            }
        }
        __syncthreads();
    }

    #pragma unroll
    for (int r = 0; r < 8; ++r) {
        int rg = rbase + rgrp * 8 + r;
        if (rg >= rows) continue;
        if (mode == 0) out[(size_t)rg * 256 + v] = acc[r];
        else {
            int node = rg / 3, m = rg % 3;
            out[(size_t)node * 256 + 64 + v * 3 + m] = acc[r];
        }
    }
}

// ---------------------------------------------------------------------------
extern "C" void kernel_launch(void* const* d_in, const int* in_sizes, int n_in,
                              void* d_out, int out_size) {
    const float* nf    = (const float*)d_in[0];
    const float* attrs = (const float*)d_in[1];
    const float* ea    = (const float*)d_in[2];
    const float* ee    = (const float*)d_in[3];
    const int*   ei    = (const int*)d_in[4];
    const float* Wl10  = (const float*)d_in[5];
    const float* Wl11  = (const float*)d_in[6];
    const float* Wfc1  = (const float*)d_in[7];
    const float* Wfc2  = (const float*)d_in[8];
    const float* Wl20  = (const float*)d_in[9];
    const float* Wl21  = (const float*)d_in[10];
    const float* Wsc0  = (const float*)d_in[11];
    const float* Wsc1  = (const float*)d_in[12];
    float* out = (float*)d_out;

    int n = in_sizes[0] / 256;
    int E = in_sizes[2] / 4;

    // launch 0: fused degree count + node-pre GEMMs (independent)
    int cb = (E + 255) / 256;
    int pre_nb0 = (n + 31) / 32, pre_nb1 = (3 * n + 31) / 32;
    fused_count_pre_kernel<<<cb + pre_nb0 + pre_nb1, 256>>>(
        ei, nf, Wl10, Wl11, E, n, cb, pre_nb0);
    // launch 1: scan -> row/cursor, re-zero g_deg
    scan_kernel<<<1, 1024>>>(n);
    // launch 2: edge MLP + packed-record scatter
    scatter_h_kernel<<<(E + 255) / 256, 256>>>(ei, ee, ea, Wfc1, E);
    // launch 3: aggregation (software-pipelined) — profiled slot
    agg_kernel<<<n, 64>>>(Wfc2, n);
    // launch 4: node post
    int post_nb0 = (n + 31) / 32, post_nb1 = (3 * n + 31) / 32;
    post_gemm_kernel<<<post_nb0 + post_nb1, 256>>>(nf, attrs, Wl20, Wl21, Wsc0, Wsc1, out, n, post_nb0);
}